// round 16
// baseline (speedup 1.0000x reference)
#include <cuda_runtime.h>
#include <cstdint>

#define S_LEN 2048
#define B_SZ  32
#define I_DIM 256
#define H_DIM 512

#define NCLUSTERS    16
#define CRANKS       8
#define ROWS_PER_CTA 64
#define REC_THREADS  512

// dynamic smem layout (bytes from base)
#define SM_TH    0          // th[2][2][512] floats            8192
#define SM_PART  8192       // part[16][128] floats            8192
#define SM_XPK   16384      // x packed: 2 bufs x 256 k x 16B  8192
#define SM_WX    24576      // Wx slice: [256 k][64 rows] f32 65536
#define SM_MBAR  90112      // 2 mbarriers                       16
#define SMEM_TOTAL 90128

// ---------------- PTX helpers ----------------
__device__ __forceinline__ uint32_t smem_u32(const void* p) {
    uint32_t a;
    asm("{ .reg .u64 t; cvta.to.shared.u64 t, %1; cvt.u32.u64 %0, t; }" : "=r"(a) : "l"(p));
    return a;
}
__device__ __forceinline__ uint32_t mapa_cluster(uint32_t addr, uint32_t rank) {
    uint32_t r;
    asm("mapa.shared::cluster.u32 %0, %1, %2;" : "=r"(r) : "r"(addr), "r"(rank));
    return r;
}
__device__ __forceinline__ void mbar_init(uint32_t mbar, uint32_t cnt) {
    asm volatile("mbarrier.init.shared.b64 [%0], %1;" :: "r"(mbar), "r"(cnt) : "memory");
}
__device__ __forceinline__ void mbar_expect_tx(uint32_t mbar, uint32_t bytes) {
    asm volatile("mbarrier.arrive.expect_tx.shared.b64 _, [%0], %1;" :: "r"(mbar), "r"(bytes) : "memory");
}
__device__ __forceinline__ void mbar_wait(uint32_t mbar, uint32_t phase) {
    uint32_t done = 0;
    while (!done) {
        asm volatile(
            "{\n\t.reg .pred p;\n\t"
            "mbarrier.try_wait.parity.acquire.cluster.shared::cta.b64 p, [%1], %2, 0x989680;\n\t"
            "selp.b32 %0, 1, 0, p;\n\t}"
            : "=r"(done) : "r"(mbar), "r"(phase) : "memory");
    }
}
__device__ __forceinline__ void st_async_b64(uint32_t daddr, unsigned long long v, uint32_t mbar) {
    asm volatile("st.async.shared::cluster.mbarrier::complete_tx::bytes.b64 [%0], %1, [%2];"
                 :: "r"(daddr), "l"(v), "r"(mbar) : "memory");
}
__device__ __forceinline__ void sts_b64(uint32_t addr, unsigned long long v) {
    asm volatile("st.shared.b64 [%0], %1;" :: "r"(addr), "l"(v) : "memory");
}
__device__ __forceinline__ unsigned long long ffma2(unsigned long long a, unsigned long long b,
                                                    unsigned long long c) {
    unsigned long long d;
    asm("fma.rn.f32x2 %0, %1, %2, %3;" : "=l"(d) : "l"(a), "l"(b), "l"(c));
    return d;
}
__device__ __forceinline__ unsigned long long add2(unsigned long long a, unsigned long long b) {
    unsigned long long d;
    asm("add.rn.f32x2 %0, %1, %2;" : "=l"(d) : "l"(a), "l"(b));
    return d;
}
__device__ __forceinline__ float fold2(unsigned long long v) {
    union { unsigned long long u; float2 f; } c; c.u = v;
    return c.f.x + c.f.y;
}
__device__ __forceinline__ unsigned long long pack2(float x, float y) {
    unsigned long long r;
    asm("mov.b64 %0, {%1, %2};" : "=l"(r) : "r"(__float_as_uint(x)), "r"(__float_as_uint(y)));
    return r;
}
__device__ __forceinline__ float fast_tanh(float h) {
    float hc = fminf(fmaxf(h, -15.f), 15.f);
    float e2 = __expf(2.f * hc);
    return __fdividef(e2 - 1.f, e2 + 1.f);
}
__device__ __forceinline__ void cluster_sync() {
    asm volatile("barrier.cluster.arrive.aligned;\n\tbarrier.cluster.wait.aligned;" ::: "memory");
}

// ---------------- fused recurrence + input projection ----------------
// 16 clusters x 8 CTAs; cluster c: batches (2c, 2c+1). CTA rank r: rows
// [r*64, r*64+64). Wh slice in registers (f32x2); Wx slice (64 rows x 256 k)
// in smem. Per step s: [prefetch x(s+1) LDG] -> x-part: warp kb accumulates
// k in [16kb,16kb+16) of x(s)@Wx into packed row-pair regs (NO dependence on
// th => runs before/through the wait stall) -> mbar wait -> R7 th GEMV ->
// partials = th-part + x-part -> STS x(s+1) packed -> __syncthreads ->
// tail t<128: reduce part[w][t], h += (v - h + bias)/tau (v includes xp!),
// tanh, pair shfl, 4x st.async.b64 to peers. out is WRITE-ONLY.
__global__ void __cluster_dims__(CRANKS, 1, 1) __launch_bounds__(REC_THREADS, 1)
rec_kernel(const float* __restrict__ x,
           const float* __restrict__ Wx,
           const float* __restrict__ Wh,
           const float* __restrict__ tau,
           const float* __restrict__ bias,
           float* __restrict__ out)
{
    extern __shared__ __align__(16) char dsm[];

    const int cid  = blockIdx.x / CRANKS;
    const int rank = blockIdx.x % CRANKS;
    const int t    = threadIdx.x;
    const int jp   = t & 31;
    const int kb   = t >> 5;
    const int j0   = 2 * jp;

    // Wh slice in registers (rows j0, j0+1; k in [kb*32, kb*32+32))
    unsigned long long wp0[16], wp1[16];
    {
        const ulonglong2* r0 = (const ulonglong2*)(Wh + (size_t)(rank * ROWS_PER_CTA + j0)     * H_DIM + kb * 32);
        const ulonglong2* r1 = (const ulonglong2*)(Wh + (size_t)(rank * ROWS_PER_CTA + j0 + 1) * H_DIM + kb * 32);
#pragma unroll
        for (int i = 0; i < 8; i++) {
            ulonglong2 a = r0[i]; wp0[2*i] = a.x; wp0[2*i+1] = a.y;
            ulonglong2 b = r1[i]; wp1[2*i] = b.x; wp1[2*i+1] = b.y;
        }
    }

    const uint32_t sbase     = smem_u32(dsm);
    const uint32_t th_base   = sbase + SM_TH;
    const uint32_t mbar_base = sbase + SM_MBAR;
    const uint32_t mbar_rel  = (uint32_t)(SM_MBAR - SM_TH);

    uint32_t peer_th[CRANKS];
#pragma unroll
    for (int r = 0; r < CRANKS; r++) peer_th[r] = mapa_cluster(th_base, r);

    // Wx slice into smem: layout [k][row] floats (u64 at [k][2jp] conflict-free)
    {
        float* Wx_f = (float*)(dsm + SM_WX);
        const float* WxG = Wx + (size_t)(rank * ROWS_PER_CTA) * I_DIM;
        for (int idx = t; idx < ROWS_PER_CTA * I_DIM; idx += REC_THREADS) {
            int r = idx >> 8;        // row 0..63
            int k = idx & 255;       // coalesced k per warp
            Wx_f[k * 64 + r] = WxG[(size_t)r * I_DIM + k];
        }
    }

    if (t == 0) {
        mbar_init(mbar_base,     1);  mbar_expect_tx(mbar_base,     4096);
        mbar_init(mbar_base + 8, 1);  mbar_expect_tx(mbar_base + 8, 4096);
    }

    // x prefetch role: thread t -> batch (t>>8), k = t&255
    const int xbt = t >> 8;
    const int xk  = t & 255;
    const float* xg = x + (size_t)(cid * 2 + xbt) * S_LEN * I_DIM + xk;
    // prologue: x for steps 0 and 1 into x_pk[0], x_pk[1]
    {
        float v0 = xg[0];
        float v1 = xg[I_DIM];
        sts_b64(sbase + SM_XPK + 0 * 4096 + xk * 16 + xbt * 8, pack2(v0, v0));
        sts_b64(sbase + SM_XPK + 1 * 4096 + xk * 16 + xbt * 8, pack2(v1, v1));
    }
    __syncthreads();
    cluster_sync();   // peers' mbars live before any st.async

    // tail state (t < 128): one (batch, row) output per thread
    const int bb = t >> 6;
    const int j  = t & 63;
    const int hg = rank * ROWS_PER_CTA + j;
    float* outp = out + (size_t)(cid * 2 + bb) * S_LEN * H_DIM + hg;

    float h = 0.f, inv_tau = 1.f, bias_r = 0.f;
    if (t < 128) {
        inv_tau = 1.0f / tau[hg];
        bias_r  = bias[hg];
    }
    const uint32_t send_off = (uint32_t)(bb * H_DIM + (hg & ~1)) * 4u;
    const int peer0 = (t & 1) * 4;   // even lane: peers 0-3, odd: peers 4-7

    // x-part: warp kb covers x-k in [16kb, 16kb+16); accumulates packed
    // (row j0, row j0+1) sums per batch. Broadcast LDS.128 (x) + LDS.64 (Wx).
#define XPART(XB, XACC0, XACC1)                                                    \
    unsigned long long XACC0 = 0ull, XACC1 = 0ull;                                 \
    {                                                                              \
        const char* xpk = dsm + SM_XPK + (XB) * 4096 + (kb * 16) * 16;             \
        const char* wxp = dsm + SM_WX + (kb * 16) * 256 + jp * 8;                  \
        _Pragma("unroll")                                                          \
        for (int kk = 0; kk < 16; kk++) {                                          \
            ulonglong2 xv = *(const ulonglong2*)(xpk + kk * 16);                   \
            unsigned long long w = *(const unsigned long long*)(wxp + kk * 256);   \
            XACC0 = ffma2(w, xv.x, XACC0);                                         \
            XACC1 = ffma2(w, xv.y, XACC1);                                         \
        }                                                                          \
    }

    // ---- step 0: th = 0, v = xp only ----
    {
        XPART(0, xacc0, xacc1)
        sts_b64(sbase + SM_PART + (uint32_t)(kb * 128 + j0) * 4u,        xacc0);
        sts_b64(sbase + SM_PART + (uint32_t)(kb * 128 + 64 + j0) * 4u,   xacc1);
        __syncthreads();
        if (t < 128) {
            const float* pf = (const float*)(dsm + SM_PART);
            float v = 0.f;
#pragma unroll
            for (int w = 0; w < 16; w++) v += pf[w * 128 + t];
            h = (v + bias_r) * inv_tau;
            float thv = fast_tanh(h);
            float tho = __shfl_xor_sync(0xffffffffu, thv, 1);
            float ho  = __shfl_xor_sync(0xffffffffu, h,   1);
            if (!(t & 1)) *(float2*)outp = make_float2(h, ho);
            unsigned long long pk = (t & 1) ? pack2(tho, thv) : pack2(thv, tho);
            uint32_t d = 4096u + send_off;                    // parity-1 buffer
            uint32_t m = mbar_rel + 8u;
#pragma unroll
            for (int rr = 0; rr < 4; rr++)
                st_async_b64(peer_th[peer0 + rr] + d, pk, peer_th[peer0 + rr] + m);
        }
    }

    uint32_t ph0 = 0, ph1 = 0;

#define STEP_BODY(STEP, P, PH, LAST)                                               \
    {                                                                              \
        float xnv = 0.f;                                                           \
        if (!(LAST)) xnv = xg[(size_t)((STEP) + 1) * I_DIM];                       \
        XPART(P, xacc0, xacc1)                                                     \
        mbar_wait(mbar_base + (P) * 8, (PH));                                      \
        if (t == 0) mbar_expect_tx(mbar_base + (P) * 8, 4096);                     \
        const ulonglong2* t0 = (const ulonglong2*)(dsm + SM_TH + (P) * 4096 + kb * 128); \
        const ulonglong2* t1 = (const ulonglong2*)(dsm + SM_TH + (P) * 4096 + 2048 + kb * 128); \
        unsigned long long a00 = 0ull, a01 = 0ull, a10 = 0ull, a11 = 0ull;         \
        _Pragma("unroll")                                                          \
        for (int i = 0; i < 8; i++) {                                              \
            ulonglong2 U = t0[i];                                                  \
            ulonglong2 V = t1[i];                                                  \
            a00 = ffma2(wp0[2*i],   U.x, a00);                                     \
            a00 = ffma2(wp0[2*i+1], U.y, a00);                                     \
            a01 = ffma2(wp1[2*i],   U.x, a01);                                     \
            a01 = ffma2(wp1[2*i+1], U.y, a01);                                     \
            a10 = ffma2(wp0[2*i],   V.x, a10);                                     \
            a10 = ffma2(wp0[2*i+1], V.y, a10);                                     \
            a11 = ffma2(wp1[2*i],   V.x, a11);                                     \
            a11 = ffma2(wp1[2*i+1], V.y, a11);                                     \
        }                                                                          \
        sts_b64(sbase + SM_PART + (uint32_t)(kb * 128 + j0) * 4u,                  \
                add2(pack2(fold2(a00), fold2(a01)), xacc0));                       \
        sts_b64(sbase + SM_PART + (uint32_t)(kb * 128 + 64 + j0) * 4u,             \
                add2(pack2(fold2(a10), fold2(a11)), xacc1));                       \
        if (!(LAST))                                                               \
            sts_b64(sbase + SM_XPK + (((P) ^ 1) * 4096) + xk * 16 + xbt * 8,       \
                    pack2(xnv, xnv));                                              \
        __syncthreads();                                                           \
        if (t < 128) {                                                             \
            const float* pf = (const float*)(dsm + SM_PART);                       \
            float v = 0.f;                                                         \
            _Pragma("unroll")                                                      \
            for (int w = 0; w < 16; w++) v += pf[w * 128 + t];                     \
            h = h + (v - h + bias_r) * inv_tau;                                    \
            float thv = fast_tanh(h);                                              \
            float tho = __shfl_xor_sync(0xffffffffu, thv, 1);                      \
            float ho  = __shfl_xor_sync(0xffffffffu, h,   1);                      \
            if (!(t & 1))                                                          \
                *(float2*)(outp + (size_t)(STEP) * H_DIM) = make_float2(h, ho);    \
            if (!(LAST)) {                                                         \
                unsigned long long pk = (t & 1) ? pack2(tho, thv)                  \
                                                : pack2(thv, tho);                 \
                uint32_t d = (uint32_t)(((P) ^ 1) * 4096) + send_off;              \
                uint32_t m = mbar_rel + (((P) ^ 1) * 8u);                          \
                _Pragma("unroll")                                                  \
                for (int rr = 0; rr < 4; rr++)                                     \
                    st_async_b64(peer_th[peer0 + rr] + d, pk,                      \
                                 peer_th[peer0 + rr] + m);                         \
            }                                                                      \
        }                                                                          \
        (PH) ^= 1;                                                                 \
    }

    for (int s = 1; s < S_LEN - 1; s += 2) {
        STEP_BODY(s,     1, ph1, 0)
        STEP_BODY(s + 1, 0, ph0, 0)
    }
    STEP_BODY(S_LEN - 1, 1, ph1, 1)
#undef STEP_BODY
#undef XPART

    cluster_sync();   // no CTA exits while peers' st.async may target its smem
}

extern "C" void kernel_launch(void* const* d_in, const int* in_sizes, int n_in,
                              void* d_out, int out_size)
{
    const float* x    = (const float*)d_in[0];
    const float* Wx   = (const float*)d_in[1];
    const float* Wh   = (const float*)d_in[2];
    const float* tau  = (const float*)d_in[3];
    const float* bias = (const float*)d_in[4];
    float* out = (float*)d_out;

    static bool attr_set = false;
    if (!attr_set) {
        cudaFuncSetAttribute(rec_kernel,
                             cudaFuncAttributeMaxDynamicSharedMemorySize,
                             SMEM_TOTAL);
        attr_set = true;
    }

    rec_kernel<<<NCLUSTERS * CRANKS, REC_THREADS, SMEM_TOTAL>>>(
        x, Wx, Wh, tau, bias, out);
}